// round 10
// baseline (speedup 1.0000x reference)
#include <cuda_runtime.h>
#include <math.h>

#define PART 888
#define NEGC (-65535.0f)
#define MAXSLOT 16

__device__ __align__(16) float g_reviewS[30000 * 64];
__device__ __align__(16) float g_tagS[40000 * 64];
__device__ __align__(16) float g_allu[10000 * 16 * 64];
__device__ __align__(16) float g_dpart[PART * 384];
__device__ __align__(16) float g_dsum[384];
__device__ __align__(16) float g_B[8 * 128];
__device__ __align__(16) float g_W[8 * 64];
__device__ int   g_akcnt[8];
__device__ int   g_acol[8 * 64];
__device__ float g_spw[8 * MAXSLOT];
__device__ int   g_spslot[8 * MAXSLOT];
__device__ int   g_colmap[64];
__device__ int   g_sparse;

// tables @ S (hoisted transform), copy B
__global__ void k_transform(const float* __restrict__ rev, const float* __restrict__ tag,
                            const float* __restrict__ S, const float* __restrict__ Bm,
                            int NR, int NT)
{
    __shared__ __align__(16) float Ssm[4096];
    __shared__ __align__(16) float er[16 * 68];
    int t = threadIdx.x;
    if (blockIdx.x == 0)
        for (int e = t; e < 1024; e += 256) g_B[e] = Bm[e];
    for (int e = t; e < 1024; e += 256)
        ((float4*)Ssm)[e] = ((const float4*)S)[e];
    __syncthreads();
    int total = NR + NT, npass = (total + 15) >> 4;
    int quad = t & 15, slot = t >> 4;
    for (int p = blockIdx.x; p < npass; p += gridDim.x) {
        int row = p * 16 + slot;
        float4 v = make_float4(0.f, 0.f, 0.f, 0.f);
        if (row < total) {
            const float4* src = (row < NR) ? (const float4*)rev + (size_t)row * 16
                                           : (const float4*)tag + (size_t)(row - NR) * 16;
            v = __ldg(src + quad);
        }
        *(float4*)&er[slot * 68 + quad * 4] = v;
        __syncthreads();
        if (row < total) {
            float4 a = make_float4(0.f, 0.f, 0.f, 0.f);
            const float* erow = &er[slot * 68];
            #pragma unroll 8
            for (int k = 0; k < 64; k++) {
                float e = erow[k];
                float4 s4 = ((const float4*)Ssm)[k * 16 + quad];
                a.x = fmaf(e, s4.x, a.x); a.y = fmaf(e, s4.y, a.y);
                a.z = fmaf(e, s4.z, a.z); a.w = fmaf(e, s4.w, a.w);
            }
            float4* dst = (row < NR) ? (float4*)g_reviewS + (size_t)row * 16
                                     : (float4*)g_tagS + (size_t)(row - NR) * 16;
            dst[quad] = a;
        }
        __syncthreads();
    }
}

// parallel reduce of delta partials: 96 blocks, one float4 column each
__global__ void k_wred()
{
    __shared__ float4 red[128];
    int e4 = blockIdx.x, t = threadIdx.x;
    float4 s = make_float4(0.f, 0.f, 0.f, 0.f);
    for (int c = t; c < PART; c += 128) {
        float4 v = ((const float4*)(g_dpart + (size_t)c * 384))[e4];
        s.x += v.x; s.y += v.y; s.z += v.z; s.w += v.w;
    }
    red[t] = s;
    __syncthreads();
    for (int o = 64; o; o >>= 1) {
        if (t < o) {
            float4 a = red[t], b2 = red[t + o];
            red[t] = make_float4(a.x + b2.x, a.y + b2.y, a.z + b2.z, a.w + b2.w);
        }
        __syncthreads();
    }
    if (t == 0) ((float4*)g_dsum)[e4] = red[0];
}

// B += delta(sum), W = softmax (exact masked), sparse metadata
__global__ void k_w(int applyK, int KC, int N)
{
    int t = threadIdx.x;
    if (applyK > 0)
        for (int e = t; e < applyK * 64; e += 256)
            g_B[(e >> 6) * 128 + (e & 63)] += g_dsum[e];
    __syncthreads();
    int w = t >> 5, lane = t & 31;
    if (w < KC) {
        float v0 = (lane      < N) ? g_B[w * 128 + lane]      : NEGC;
        float v1 = (lane + 32 < N) ? g_B[w * 128 + lane + 32] : NEGC;
        float m = fmaxf(fmaxf(v0, v1), NEGC);
        #pragma unroll
        for (int o = 16; o; o >>= 1) m = fmaxf(m, __shfl_xor_sync(~0u, m, o));
        float e0 = expf(v0 - m), e1 = expf(v1 - m);
        float s = e0 + e1 + 2.f * expf(NEGC - m);  // cols 64..127 all NEGC
        #pragma unroll
        for (int o = 16; o; o >>= 1) s += __shfl_xor_sync(~0u, s, o);
        float inv = 1.f / s;
        float w0 = e0 * inv, w1 = e1 * inv;
        g_W[w * 64 + lane]      = w0;
        g_W[w * 64 + lane + 32] = w1;
        unsigned m0 = __ballot_sync(~0u, w0 != 0.f);
        unsigned m1 = __ballot_sync(~0u, w1 != 0.f);
        if (lane == 0) {
            int c = 0;
            for (int j = 0; j < 32; j++) if ((m0 >> j) & 1) g_acol[w * 64 + c++] = j;
            for (int j = 0; j < 32; j++) if ((m1 >> j) & 1) g_acol[w * 64 + c++] = j + 32;
            g_akcnt[w] = c;
        }
    }
    __syncthreads();
    if (t == 0) {
        int map[64];
        for (int j = 0; j < 64; j++) map[j] = -1;
        int cnt = 0;
        for (int k = 0; k < KC; k++) {
            int c = g_akcnt[k];
            for (int j = 0; j < c; j++) {
                int n = g_acol[k * 64 + j];
                if (map[n] < 0) { if (cnt < MAXSLOT) map[n] = cnt; cnt++; }
                if (j < MAXSLOT) {
                    g_spw[k * MAXSLOT + j] = g_W[k * 64 + n];
                    g_spslot[k * MAXSLOT + j] = map[n];
                }
            }
        }
        for (int j = 0; j < 64; j++) g_colmap[j] = map[j];
        g_sparse = (cnt <= MAXSLOT) ? 1 : 0;
    }
}

// one routing iteration (no long register live ranges -> no spills)
template <int KC, int N, int NQ>
__global__ void __launch_bounds__(256) k_route(
        const int* __restrict__ idx, int tsel, int NB,
        int slotBase, int writeHigh, int compDelta)
{
    constexpr int LNQ = (NQ == 8) ? 3 : 2;
    constexpr int DC = 64 / NQ;          // d per thread (16 or 8)
    constexpr int NDMAX = 256 >> LNQ;    // rows covered (64 or 32)
    __shared__ __align__(16) float low[N * 68];
    __shared__ __align__(16) float act_low[MAXSLOT * 68];
    __shared__ __align__(16) float wsm[KC * 64];
    __shared__ __align__(16) float scratch[4 * KC * 64];
    __shared__ __align__(16) float xfull[KC * 64];
    __shared__ __align__(16) float hsm[KC * 64];
    __shared__ float spw_s[KC * MAXSLOT];
    __shared__ int spslot_s[KC * MAXSLOT];
    __shared__ int akcnt_s[8];
    __shared__ int colmap_s[64];
    __shared__ int sp_s;

    const float* table = tsel ? g_tagS : g_reviewS;
    int t = threadIdx.x;
    for (int e = t; e < KC * 64; e += 256) wsm[e] = g_W[e];
    if (t < KC * MAXSLOT) { spw_s[t] = g_spw[t]; spslot_s[t] = g_spslot[t]; }
    if (t < 64) colmap_s[t] = g_colmap[t];
    if (t < 8) akcnt_s[t] = g_akcnt[t];
    if (t == 0) sp_s = g_sparse;
    __syncthreads();
    int sp = sp_s;

    int nD = t >> LNQ, qD = t & (NQ - 1);
    bool vn = (nD < N);
    float dreg[KC];
    #pragma unroll
    for (int k = 0; k < KC; k++) dreg[k] = 0.f;

    for (int b = blockIdx.x; b < NB; b += gridDim.x) {
        const int* ib = idx + (size_t)b * N;
        const float4* rowp = vn ? (const float4*)(table + (size_t)__ldg(ib + nD) * 64) + qD * (DC / 4)
                                : (const float4*)0;
        // gather phase: dense -> full low tile; sparse -> only active rows
        if (sp) {
            int s = vn ? colmap_s[nD] : -1;
            if (s >= 0)
                #pragma unroll
                for (int j = 0; j < DC / 4; j++)
                    *(float4*)&act_low[s * 68 + qD * DC + 4 * j] = __ldg(rowp + j);
        } else if (vn) {
            #pragma unroll
            for (int j = 0; j < DC / 4; j++)
                *(float4*)&low[nD * 68 + qD * DC + 4 * j] = __ldg(rowp + j);
        }
        __syncthreads();

        if (!sp) {  // dense x: thread (d, qx) streams 16 n
            int d = t & 63, qx = t >> 6;
            float ax[KC];
            #pragma unroll
            for (int k = 0; k < KC; k++) ax[k] = 0.f;
            int lo = qx * 16, hi = min(N, lo + 16), nv = lo + ((hi - lo) & ~3);
            for (int n = lo; n < nv; n += 4) {
                float f0 = low[(n+0)*68+d], f1 = low[(n+1)*68+d];
                float f2 = low[(n+2)*68+d], f3 = low[(n+3)*68+d];
                #pragma unroll
                for (int k = 0; k < KC; k++) {
                    float4 w4 = *(const float4*)&wsm[k * 64 + n];
                    ax[k] = fmaf(w4.x, f0, fmaf(w4.y, f1, fmaf(w4.z, f2, fmaf(w4.w, f3, ax[k]))));
                }
            }
            for (int n = nv; n < hi; n++) {
                float f = low[n * 68 + d];
                #pragma unroll
                for (int k = 0; k < KC; k++) ax[k] = fmaf(wsm[k * 64 + n], f, ax[k]);
            }
            #pragma unroll
            for (int k = 0; k < KC; k++) scratch[qx * (KC*64) + k * 64 + d] = ax[k];
            __syncthreads();
            for (int e = t; e < KC * 64; e += 256)
                xfull[e] = scratch[e] + scratch[KC*64 + e] + scratch[2*KC*64 + e] + scratch[3*KC*64 + e];
            __syncthreads();
        }

        if (t < 64) {  // squash + high (+ output write)
            float xk[KC];
            if (sp) {
                #pragma unroll
                for (int k = 0; k < KC; k++) {
                    float s = 0.f;
                    int c = akcnt_s[k];
                    for (int j = 0; j < c; j++)
                        s = fmaf(spw_s[k * MAXSLOT + j], act_low[spslot_s[k * MAXSLOT + j] * 68 + t], s);
                    xk[k] = s;
                }
            } else {
                #pragma unroll
                for (int k = 0; k < KC; k++) xk[k] = xfull[k * 64 + t];
            }
            float sq = 0.f;
            #pragma unroll
            for (int k = 0; k < KC; k++) sq += xk[k] * xk[k];
            float f = sq / (1.f + sq) / sqrtf(sq + 1e-9f);
            #pragma unroll
            for (int k = 0; k < KC; k++) {
                float h = f * xk[k];
                if (compDelta) hsm[k * 64 + t] = h;
                if (writeHigh)
                    g_allu[(size_t)b * 1024 + (size_t)(slotBase + k) * 64 + t] = h;
            }
        }

        if (compDelta) {
            __syncthreads();  // hsm ready
            float ad[KC];
            #pragma unroll
            for (int k = 0; k < KC; k++) ad[k] = 0.f;
            if (vn) {
                #pragma unroll
                for (int j4 = 0; j4 < DC; j4 += 4) {
                    // re-read own row: dense from smem tile, sparse fresh from L2
                    float4 lv = sp ? __ldg(rowp + (j4 >> 2))
                                   : *(const float4*)&low[nD * 68 + qD * DC + j4];
                    int d0 = qD * DC + j4;
                    #pragma unroll
                    for (int k = 0; k < KC; k++) {
                        float4 h4 = *(const float4*)&hsm[k * 64 + d0];
                        ad[k] = fmaf(h4.x, lv.x, fmaf(h4.y, lv.y,
                                fmaf(h4.z, lv.z, fmaf(h4.w, lv.w, ad[k]))));
                    }
                }
            }
            #pragma unroll
            for (int k = 0; k < KC; k++) {
                #pragma unroll
                for (int o = NQ >> 1; o; o >>= 1)
                    ad[k] += __shfl_xor_sync(~0u, ad[k], o);
                dreg[k] += ad[k];
            }
        }
        __syncthreads();  // buffer reuse guard
    }

    if (compDelta) {
        if (qD == 0)
            #pragma unroll
            for (int k = 0; k < KC; k++)
                g_dpart[(size_t)blockIdx.x * 384 + k * 64 + nD] = dreg[k];
        for (int e = t; e < KC * 64; e += 256)
            if ((e & 63) >= NDMAX)
                g_dpart[(size_t)blockIdx.x * 384 + e] = 0.f;
    }
}

// attention readout: 16 real capsules + 8 phantom (s=0 exactly)
__global__ void k_final(const float* __restrict__ M1, const float* __restrict__ M2,
                        float* __restrict__ out, int NB)
{
    __shared__ __align__(16) float M1s[4096];
    __shared__ float M2s[64];
    __shared__ __align__(16) float usm[16 * 68];
    __shared__ float ssm[16], attsm[16];
    int t = threadIdx.x;
    for (int e = t; e < 1024; e += 256) ((float4*)M1s)[e] = ((const float4*)M1)[e];
    if (t < 64) M2s[t] = M2[t];
    __syncthreads();
    int e4 = t & 15, k = t >> 4;
    for (int b = blockIdx.x; b < NB; b += gridDim.x) {
        float4 u4 = __ldg((const float4*)g_allu + (size_t)b * 256 + k * 16 + e4);
        *(float4*)&usm[k * 68 + e4 * 4] = u4;
        __syncthreads();
        float4 v = make_float4(0.f, 0.f, 0.f, 0.f);
        const float* urow = &usm[k * 68];
        #pragma unroll 8
        for (int dd = 0; dd < 64; dd++) {
            float u = urow[dd];
            float4 m4 = ((const float4*)M1s)[dd * 16 + e4];
            v.x = fmaf(u, m4.x, v.x); v.y = fmaf(u, m4.y, v.y);
            v.z = fmaf(u, m4.z, v.z); v.w = fmaf(u, m4.w, v.w);
        }
        float c = tanhf(v.x) * M2s[e4*4] + tanhf(v.y) * M2s[e4*4+1]
                + tanhf(v.z) * M2s[e4*4+2] + tanhf(v.w) * M2s[e4*4+3];
        #pragma unroll
        for (int o = 8; o; o >>= 1) c += __shfl_down_sync(~0u, c, o, 16);
        if (e4 == 0) ssm[k] = c * c;
        __syncthreads();
        if (t < 32) {
            float sv = (t < 16) ? ssm[t] : 0.f;
            float m = sv;
            #pragma unroll
            for (int o = 16; o; o >>= 1) m = fmaxf(m, __shfl_xor_sync(~0u, m, o));
            float ev = (t < 24) ? expf(sv - m) : 0.f;
            float s = ev;
            #pragma unroll
            for (int o = 16; o; o >>= 1) s += __shfl_xor_sync(~0u, s, o);
            if (t < 16) attsm[t] = ev / s;
        }
        __syncthreads();
        if (t < 64) {
            float o = 0.f;
            #pragma unroll
            for (int kk = 0; kk < 16; kk++) o = fmaf(attsm[kk], usm[kk * 68 + t], o);
            out[(size_t)b * 64 + t] = o;
        }
        __syncthreads();
    }
}

// review_out = mean(tag_embed[idx_rht], axis=1)  (raw tag table)
__global__ void k_review(const float* __restrict__ tag, const int* __restrict__ idx,
                         float* __restrict__ out, int NB)
{
    int t = threadIdx.x, w = t >> 5, l = t & 31;
    int b = blockIdx.x * 8 + w;
    if (b >= NB) return;
    const int* ib = idx + (size_t)b * 20;
    float a0 = 0.f, a1 = 0.f;
    #pragma unroll
    for (int r = 0; r < 20; r++) {
        const float* row = tag + (size_t)__ldg(ib + r) * 64;
        a0 += __ldg(row + l); a1 += __ldg(row + l + 32);
    }
    out[(size_t)b * 64 + l] = a0 / 20.0f;
    out[(size_t)b * 64 + l + 32] = a1 / 20.0f;
}

extern "C" void kernel_launch(void* const* d_in, const int* in_sizes, int n_in,
                              void* d_out, int out_size)
{
    const float* rev = (const float*)d_in[0];
    const float* tag = (const float*)d_in[1];
    const int* idx_urt  = (const int*)d_in[2];
    const int* idx_uqt  = (const int*)d_in[3];
    const int* idx_uprt = (const int*)d_in[4];
    const int* idx_rht  = (const int*)d_in[5];
    const float* Bm = (const float*)d_in[6];
    const float* S  = (const float*)d_in[7];
    const float* M1 = (const float*)d_in[8];
    const float* M2 = (const float*)d_in[9];
    float* out = (float*)d_out;
    int NR = in_sizes[0] / 64, NT = in_sizes[1] / 64;
    int NU = in_sizes[2] / 64, NRD = in_sizes[5] / 20;

    k_transform<<<592, 256>>>(rev, tag, S, Bm, NR, NT);
    k_review<<<(NRD + 7) / 8, 256>>>(tag, idx_rht, out + (size_t)NU * 64, NRD);

    // routing 0: idx_urt over reviewS, n=64, K=6, slots 0..5
    k_w<<<1, 256>>>(0, 6, 64);
    k_route<6, 64, 4><<<PART, 256>>>(idx_urt, 0, NU, 0, 0, 1);
    k_wred<<<96, 128>>>(); k_w<<<1, 256>>>(6, 6, 64);
    k_route<6, 64, 4><<<PART, 256>>>(idx_urt, 0, NU, 0, 0, 1);
    k_wred<<<96, 128>>>(); k_w<<<1, 256>>>(6, 6, 64);
    k_route<6, 64, 4><<<PART, 256>>>(idx_urt, 0, NU, 0, 1, 1);
    // routing 1: idx_uqt over tagS, n=32, K=5, slots 6..10
    k_wred<<<96, 128>>>(); k_w<<<1, 256>>>(6, 5, 32);
    k_route<5, 32, 8><<<PART, 256>>>(idx_uqt, 1, NU, 6, 0, 1);
    k_wred<<<96, 128>>>(); k_w<<<1, 256>>>(5, 5, 32);
    k_route<5, 32, 8><<<PART, 256>>>(idx_uqt, 1, NU, 6, 0, 1);
    k_wred<<<96, 128>>>(); k_w<<<1, 256>>>(5, 5, 32);
    k_route<5, 32, 8><<<PART, 256>>>(idx_uqt, 1, NU, 6, 1, 1);
    // routing 2: idx_uprt over reviewS, n=50, K=5, slots 11..15 (last delta dead)
    k_wred<<<96, 128>>>(); k_w<<<1, 256>>>(5, 5, 50);
    k_route<5, 50, 4><<<PART, 256>>>(idx_uprt, 0, NU, 11, 0, 1);
    k_wred<<<96, 128>>>(); k_w<<<1, 256>>>(5, 5, 50);
    k_route<5, 50, 4><<<PART, 256>>>(idx_uprt, 0, NU, 11, 0, 1);
    k_wred<<<96, 128>>>(); k_w<<<1, 256>>>(5, 5, 50);
    k_route<5, 50, 4><<<PART, 256>>>(idx_uprt, 0, NU, 11, 1, 0);

    k_final<<<592, 256>>>(M1, M2, out, NU);
}

// round 11
// speedup vs baseline: 1.1899x; 1.1899x over previous
#include <cuda_runtime.h>
#include <math.h>

#define PART 592
#define NEGC (-65535.0f)

__device__ __align__(16) float g_reviewS[30000 * 64];
__device__ __align__(16) float g_tagS[40000 * 64];
__device__ __align__(16) float g_allu[10000 * 16 * 64];
__device__ __align__(16) float g_dpart[PART * 384];
__device__ __align__(16) float g_dsum[384];
__device__ __align__(16) float g_B[8 * 128];
__device__ __align__(16) float g_W[8 * 64];
__device__ int g_akcnt[8];
__device__ int g_acol[8 * 64];
__device__ int g_sparse;

// tables @ S (hoisted transform), copy B
__global__ void k_transform(const float* __restrict__ rev, const float* __restrict__ tag,
                            const float* __restrict__ S, const float* __restrict__ Bm,
                            int NR, int NT)
{
    __shared__ __align__(16) float Ssm[4096];
    __shared__ __align__(16) float er[16 * 68];
    int t = threadIdx.x;
    if (blockIdx.x == 0)
        for (int e = t; e < 1024; e += 256) g_B[e] = Bm[e];
    for (int e = t; e < 1024; e += 256)
        ((float4*)Ssm)[e] = ((const float4*)S)[e];
    __syncthreads();
    int total = NR + NT, npass = (total + 15) >> 4;
    int quad = t & 15, slot = t >> 4;
    for (int p = blockIdx.x; p < npass; p += gridDim.x) {
        int row = p * 16 + slot;
        float4 v = make_float4(0.f, 0.f, 0.f, 0.f);
        if (row < total) {
            const float4* src = (row < NR) ? (const float4*)rev + (size_t)row * 16
                                           : (const float4*)tag + (size_t)(row - NR) * 16;
            v = __ldg(src + quad);
        }
        *(float4*)&er[slot * 68 + quad * 4] = v;
        __syncthreads();
        if (row < total) {
            float4 a = make_float4(0.f, 0.f, 0.f, 0.f);
            const float* erow = &er[slot * 68];
            #pragma unroll 8
            for (int k = 0; k < 64; k++) {
                float e = erow[k];
                float4 s4 = ((const float4*)Ssm)[k * 16 + quad];
                a.x = fmaf(e, s4.x, a.x); a.y = fmaf(e, s4.y, a.y);
                a.z = fmaf(e, s4.z, a.z); a.w = fmaf(e, s4.w, a.w);
            }
            float4* dst = (row < NR) ? (float4*)g_reviewS + (size_t)row * 16
                                     : (float4*)g_tagS + (size_t)(row - NR) * 16;
            dst[quad] = a;
        }
        __syncthreads();
    }
}

// parallel reduce of delta partials: 96 blocks, one float4 column each
__global__ void k_wred()
{
    __shared__ float4 red[128];
    int e4 = blockIdx.x, t = threadIdx.x;
    float4 s = make_float4(0.f, 0.f, 0.f, 0.f);
    for (int c = t; c < PART; c += 128) {
        float4 v = ((const float4*)(g_dpart + (size_t)c * 384))[e4];
        s.x += v.x; s.y += v.y; s.z += v.z; s.w += v.w;
    }
    red[t] = s;
    __syncthreads();
    for (int o = 64; o; o >>= 1) {
        if (t < o) {
            float4 a = red[t], b2 = red[t + o];
            red[t] = make_float4(a.x + b2.x, a.y + b2.y, a.z + b2.z, a.w + b2.w);
        }
        __syncthreads();
    }
    if (t == 0) ((float4*)g_dsum)[e4] = red[0];
}

// B += delta(sum), W = softmax (exact masked), active-column metadata
__global__ void k_w(int applyK, int KC, int N)
{
    int t = threadIdx.x;
    if (applyK > 0)
        for (int e = t; e < applyK * 64; e += 256)
            g_B[(e >> 6) * 128 + (e & 63)] += g_dsum[e];
    __syncthreads();
    int w = t >> 5, lane = t & 31;
    if (w < KC) {
        float v0 = (lane      < N) ? g_B[w * 128 + lane]      : NEGC;
        float v1 = (lane + 32 < N) ? g_B[w * 128 + lane + 32] : NEGC;
        float m = fmaxf(fmaxf(v0, v1), NEGC);
        #pragma unroll
        for (int o = 16; o; o >>= 1) m = fmaxf(m, __shfl_xor_sync(~0u, m, o));
        float e0 = expf(v0 - m), e1 = expf(v1 - m);
        float s = e0 + e1 + 2.f * expf(NEGC - m);  // cols 64..127 all NEGC
        #pragma unroll
        for (int o = 16; o; o >>= 1) s += __shfl_xor_sync(~0u, s, o);
        float inv = 1.f / s;
        float w0 = e0 * inv, w1 = e1 * inv;
        g_W[w * 64 + lane]      = w0;
        g_W[w * 64 + lane + 32] = w1;
        unsigned m0 = __ballot_sync(~0u, w0 != 0.f);
        unsigned m1 = __ballot_sync(~0u, w1 != 0.f);
        if (lane == 0) {
            int c = 0;
            for (int j = 0; j < 32; j++) if ((m0 >> j) & 1) g_acol[w * 64 + c++] = j;
            for (int j = 0; j < 32; j++) if ((m1 >> j) & 1) g_acol[w * 64 + c++] = j + 32;
            g_akcnt[w] = c;
        }
    }
    __syncthreads();
    if (t == 0) {
        int tot = 0;
        for (int k = 0; k < KC; k++) tot += g_akcnt[k];
        g_sparse = (tot <= 48) ? 1 : 0;
    }
}

// one routing iteration: high = squash(W @ low), delta = sum_b high @ low^T
template <int KC, int N, int NQ>
__global__ void __launch_bounds__(256) k_route(
        const int* __restrict__ idx, int tsel, int NB,
        int slotBase, int writeHigh, int compDelta)
{
    constexpr int LNQ = (NQ == 8) ? 3 : 2;
    constexpr int DC = 64 / NQ;          // d per thread in delta (16 or 8)
    constexpr int NDMAX = 256 >> LNQ;    // rows covered by delta layout (64 or 32)
    __shared__ __align__(16) float low[N * 68];
    __shared__ __align__(16) float wsm[KC * 64];
    __shared__ __align__(16) float scratch[4 * KC * 64];
    __shared__ __align__(16) float xfull[KC * 64];
    __shared__ __align__(16) float hsm[KC * 64];
    __shared__ int acol_s[KC * 64];
    __shared__ int akcnt_s[8];
    __shared__ int sp_s;

    const float* table = tsel ? g_tagS : g_reviewS;
    int t = threadIdx.x;
    for (int e = t; e < KC * 64; e += 256) { wsm[e] = g_W[e]; acol_s[e] = g_acol[e]; }
    if (t < 8) akcnt_s[t] = g_akcnt[t];
    if (t == 0) sp_s = g_sparse;
    __syncthreads();
    int sp = sp_s;

    int nD = t >> LNQ, qD = t & (NQ - 1);
    bool vn = (nD < N);
    float dreg[KC];
    #pragma unroll
    for (int k = 0; k < KC; k++) dreg[k] = 0.f;

    for (int b = blockIdx.x; b < NB; b += gridDim.x) {
        const int* ib = idx + (size_t)b * N;
        // full gather -> smem tile (the LDG floor; reused by x and delta)
        for (int e = t; e < N * 16; e += 256) {
            int r = e >> 4, c = e & 15;
            float4 v = __ldg((const float4*)table + (size_t)__ldg(ib + r) * 16 + c);
            *(float4*)&low[r * 68 + c * 4] = v;
        }
        __syncthreads();

        if (!sp) {  // dense x: thread (d, qx) streams 16 n, scratch reduce
            int d = t & 63, qx = t >> 6;
            float ax[KC];
            #pragma unroll
            for (int k = 0; k < KC; k++) ax[k] = 0.f;
            int lo = qx * 16, hi = min(N, lo + 16), nv = lo + ((hi - lo) & ~3);
            for (int n = lo; n < nv; n += 4) {
                float f0 = low[(n+0)*68+d], f1 = low[(n+1)*68+d];
                float f2 = low[(n+2)*68+d], f3 = low[(n+3)*68+d];
                #pragma unroll
                for (int k = 0; k < KC; k++) {
                    float4 w4 = *(const float4*)&wsm[k * 64 + n];
                    ax[k] = fmaf(w4.x, f0, fmaf(w4.y, f1, fmaf(w4.z, f2, fmaf(w4.w, f3, ax[k]))));
                }
            }
            for (int n = nv; n < hi; n++) {
                float f = low[n * 68 + d];
                #pragma unroll
                for (int k = 0; k < KC; k++) ax[k] = fmaf(wsm[k * 64 + n], f, ax[k]);
            }
            #pragma unroll
            for (int k = 0; k < KC; k++) scratch[qx * (KC*64) + k * 64 + d] = ax[k];
            __syncthreads();
            for (int e = t; e < KC * 64; e += 256)
                xfull[e] = scratch[e] + scratch[KC*64 + e] + scratch[2*KC*64 + e] + scratch[3*KC*64 + e];
            __syncthreads();
        }

        if (t < 64) {  // (sparse x) + squash + high write
            float xk[KC];
            if (sp) {
                #pragma unroll
                for (int k = 0; k < KC; k++) {
                    float s = 0.f;
                    int c = akcnt_s[k];
                    for (int j = 0; j < c; j++) {
                        int n = acol_s[k * 64 + j];
                        s = fmaf(wsm[k * 64 + n], low[n * 68 + t], s);
                    }
                    xk[k] = s;
                }
            } else {
                #pragma unroll
                for (int k = 0; k < KC; k++) xk[k] = xfull[k * 64 + t];
            }
            float sq = 0.f;
            #pragma unroll
            for (int k = 0; k < KC; k++) sq += xk[k] * xk[k];
            float f = sq / (1.f + sq) / sqrtf(sq + 1e-9f);
            #pragma unroll
            for (int k = 0; k < KC; k++) {
                float h = f * xk[k];
                if (compDelta) hsm[k * 64 + t] = h;
                if (writeHigh)
                    g_allu[(size_t)b * 1024 + (size_t)(slotBase + k) * 64 + t] = h;
            }
        }

        if (compDelta) {
            __syncthreads();  // hsm ready
            float ad[KC];
            #pragma unroll
            for (int k = 0; k < KC; k++) ad[k] = 0.f;
            if (vn) {
                #pragma unroll
                for (int j4 = 0; j4 < DC; j4 += 4) {
                    float4 lv = *(const float4*)&low[nD * 68 + qD * DC + j4];
                    int d0 = qD * DC + j4;
                    #pragma unroll
                    for (int k = 0; k < KC; k++) {
                        float4 h4 = *(const float4*)&hsm[k * 64 + d0];
                        ad[k] = fmaf(h4.x, lv.x, fmaf(h4.y, lv.y,
                                fmaf(h4.z, lv.z, fmaf(h4.w, lv.w, ad[k]))));
                    }
                }
            }
            #pragma unroll
            for (int k = 0; k < KC; k++) {
                #pragma unroll
                for (int o = NQ >> 1; o; o >>= 1)
                    ad[k] += __shfl_xor_sync(~0u, ad[k], o);
                dreg[k] += ad[k];
            }
        }
        __syncthreads();  // buffer reuse guard
    }

    if (compDelta) {
        if (qD == 0)
            #pragma unroll
            for (int k = 0; k < KC; k++)
                g_dpart[(size_t)blockIdx.x * 384 + k * 64 + nD] = dreg[k];
        for (int e = t; e < KC * 64; e += 256)
            if ((e & 63) >= NDMAX)
                g_dpart[(size_t)blockIdx.x * 384 + e] = 0.f;
    }
}

// attention readout: 16 real capsules + 8 phantom (s=0 exactly)
__global__ void k_final(const float* __restrict__ M1, const float* __restrict__ M2,
                        float* __restrict__ out, int NB)
{
    __shared__ __align__(16) float M1s[4096];
    __shared__ float M2s[64];
    __shared__ __align__(16) float usm[16 * 68];
    __shared__ float ssm[16], attsm[16];
    int t = threadIdx.x;
    for (int e = t; e < 1024; e += 256) ((float4*)M1s)[e] = ((const float4*)M1)[e];
    if (t < 64) M2s[t] = M2[t];
    __syncthreads();
    int e4 = t & 15, k = t >> 4;
    for (int b = blockIdx.x; b < NB; b += gridDim.x) {
        float4 u4 = __ldg((const float4*)g_allu + (size_t)b * 256 + k * 16 + e4);
        *(float4*)&usm[k * 68 + e4 * 4] = u4;
        __syncthreads();
        float4 v = make_float4(0.f, 0.f, 0.f, 0.f);
        const float* urow = &usm[k * 68];
        #pragma unroll 8
        for (int dd = 0; dd < 64; dd++) {
            float u = urow[dd];
            float4 m4 = ((const float4*)M1s)[dd * 16 + e4];
            v.x = fmaf(u, m4.x, v.x); v.y = fmaf(u, m4.y, v.y);
            v.z = fmaf(u, m4.z, v.z); v.w = fmaf(u, m4.w, v.w);
        }
        float c = tanhf(v.x) * M2s[e4*4] + tanhf(v.y) * M2s[e4*4+1]
                + tanhf(v.z) * M2s[e4*4+2] + tanhf(v.w) * M2s[e4*4+3];
        #pragma unroll
        for (int o = 8; o; o >>= 1) c += __shfl_down_sync(~0u, c, o, 16);
        if (e4 == 0) ssm[k] = c * c;
        __syncthreads();
        if (t < 32) {
            float sv = (t < 16) ? ssm[t] : 0.f;
            float m = sv;
            #pragma unroll
            for (int o = 16; o; o >>= 1) m = fmaxf(m, __shfl_xor_sync(~0u, m, o));
            float ev = (t < 24) ? expf(sv - m) : 0.f;
            float s = ev;
            #pragma unroll
            for (int o = 16; o; o >>= 1) s += __shfl_xor_sync(~0u, s, o);
            if (t < 16) attsm[t] = ev / s;
        }
        __syncthreads();
        if (t < 64) {
            float o = 0.f;
            #pragma unroll
            for (int kk = 0; kk < 16; kk++) o = fmaf(attsm[kk], usm[kk * 68 + t], o);
            out[(size_t)b * 64 + t] = o;
        }
        __syncthreads();
    }
}

// review_out = mean(tag_embed[idx_rht], axis=1)  (raw tag table)
__global__ void k_review(const float* __restrict__ tag, const int* __restrict__ idx,
                         float* __restrict__ out, int NB)
{
    int t = threadIdx.x, w = t >> 5, l = t & 31;
    int b = blockIdx.x * 8 + w;
    if (b >= NB) return;
    const int* ib = idx + (size_t)b * 20;
    float a0 = 0.f, a1 = 0.f;
    #pragma unroll
    for (int r = 0; r < 20; r++) {
        const float* row = tag + (size_t)__ldg(ib + r) * 64;
        a0 += __ldg(row + l); a1 += __ldg(row + l + 32);
    }
    out[(size_t)b * 64 + l] = a0 / 20.0f;
    out[(size_t)b * 64 + l + 32] = a1 / 20.0f;
}

extern "C" void kernel_launch(void* const* d_in, const int* in_sizes, int n_in,
                              void* d_out, int out_size)
{
    const float* rev = (const float*)d_in[0];
    const float* tag = (const float*)d_in[1];
    const int* idx_urt  = (const int*)d_in[2];
    const int* idx_uqt  = (const int*)d_in[3];
    const int* idx_uprt = (const int*)d_in[4];
    const int* idx_rht  = (const int*)d_in[5];
    const float* Bm = (const float*)d_in[6];
    const float* S  = (const float*)d_in[7];
    const float* M1 = (const float*)d_in[8];
    const float* M2 = (const float*)d_in[9];
    float* out = (float*)d_out;
    int NR = in_sizes[0] / 64, NT = in_sizes[1] / 64;
    int NU = in_sizes[2] / 64, NRD = in_sizes[5] / 20;

    k_transform<<<592, 256>>>(rev, tag, S, Bm, NR, NT);
    k_review<<<(NRD + 7) / 8, 256>>>(tag, idx_rht, out + (size_t)NU * 64, NRD);

    // routing 0: idx_urt over reviewS, n=64, K=6, slots 0..5
    k_w<<<1, 256>>>(0, 6, 64);
    k_route<6, 64, 4><<<PART, 256>>>(idx_urt, 0, NU, 0, 0, 1);
    k_wred<<<96, 128>>>(); k_w<<<1, 256>>>(6, 6, 64);
    k_route<6, 64, 4><<<PART, 256>>>(idx_urt, 0, NU, 0, 0, 1);
    k_wred<<<96, 128>>>(); k_w<<<1, 256>>>(6, 6, 64);
    k_route<6, 64, 4><<<PART, 256>>>(idx_urt, 0, NU, 0, 1, 1);
    // routing 1: idx_uqt over tagS, n=32, K=5, slots 6..10
    k_wred<<<96, 128>>>(); k_w<<<1, 256>>>(6, 5, 32);
    k_route<5, 32, 8><<<PART, 256>>>(idx_uqt, 1, NU, 6, 0, 1);
    k_wred<<<96, 128>>>(); k_w<<<1, 256>>>(5, 5, 32);
    k_route<5, 32, 8><<<PART, 256>>>(idx_uqt, 1, NU, 6, 0, 1);
    k_wred<<<96, 128>>>(); k_w<<<1, 256>>>(5, 5, 32);
    k_route<5, 32, 8><<<PART, 256>>>(idx_uqt, 1, NU, 6, 1, 1);
    // routing 2: idx_uprt over reviewS, n=50, K=5, slots 11..15 (last delta dead)
    k_wred<<<96, 128>>>(); k_w<<<1, 256>>>(5, 5, 50);
    k_route<5, 50, 4><<<PART, 256>>>(idx_uprt, 0, NU, 11, 0, 1);
    k_wred<<<96, 128>>>(); k_w<<<1, 256>>>(5, 5, 50);
    k_route<5, 50, 4><<<PART, 256>>>(idx_uprt, 0, NU, 11, 0, 1);
    k_wred<<<96, 128>>>(); k_w<<<1, 256>>>(5, 5, 50);
    k_route<5, 50, 4><<<PART, 256>>>(idx_uprt, 0, NU, 11, 1, 0);

    k_final<<<592, 256>>>(M1, M2, out, NU);
}

// round 12
// speedup vs baseline: 1.2434x; 1.0450x over previous
#include <cuda_runtime.h>
#include <math.h>

#define PART 592
#define NEGC (-65535.0f)

__device__ __align__(16) float g_reviewS[30000 * 64];
__device__ __align__(16) float g_tagS[40000 * 64];
__device__ __align__(16) float g_allu[10000 * 16 * 64];
__device__ __align__(16) float g_dpart[PART * 384];
__device__ __align__(16) float g_dsum[384];
__device__ __align__(16) float g_B[8 * 128];
__device__ __align__(16) float g_W[8 * 64];
__device__ int g_akcnt[8];
__device__ int g_acol[8 * 64];
__device__ int g_sparse;

// tables @ S (hoisted transform), copy B
__global__ void k_transform(const float* __restrict__ rev, const float* __restrict__ tag,
                            const float* __restrict__ S, const float* __restrict__ Bm,
                            int NR, int NT)
{
    __shared__ __align__(16) float Ssm[4096];
    __shared__ __align__(16) float er[16 * 68];
    int t = threadIdx.x;
    if (blockIdx.x == 0)
        for (int e = t; e < 1024; e += 256) g_B[e] = Bm[e];
    for (int e = t; e < 1024; e += 256)
        ((float4*)Ssm)[e] = ((const float4*)S)[e];
    __syncthreads();
    int total = NR + NT, npass = (total + 15) >> 4;
    int quad = t & 15, slot = t >> 4;
    for (int p = blockIdx.x; p < npass; p += gridDim.x) {
        int row = p * 16 + slot;
        float4 v = make_float4(0.f, 0.f, 0.f, 0.f);
        if (row < total) {
            const float4* src = (row < NR) ? (const float4*)rev + (size_t)row * 16
                                           : (const float4*)tag + (size_t)(row - NR) * 16;
            v = __ldg(src + quad);
        }
        *(float4*)&er[slot * 68 + quad * 4] = v;
        __syncthreads();
        if (row < total) {
            float4 a = make_float4(0.f, 0.f, 0.f, 0.f);
            const float* erow = &er[slot * 68];
            #pragma unroll 8
            for (int k = 0; k < 64; k++) {
                float e = erow[k];
                float4 s4 = ((const float4*)Ssm)[k * 16 + quad];
                a.x = fmaf(e, s4.x, a.x); a.y = fmaf(e, s4.y, a.y);
                a.z = fmaf(e, s4.z, a.z); a.w = fmaf(e, s4.w, a.w);
            }
            float4* dst = (row < NR) ? (float4*)g_reviewS + (size_t)row * 16
                                     : (float4*)g_tagS + (size_t)(row - NR) * 16;
            dst[quad] = a;
        }
        __syncthreads();
    }
}

// parallel reduce of delta partials
__global__ void k_wred()
{
    __shared__ float4 red[128];
    int e4 = blockIdx.x, t = threadIdx.x;
    float4 s = make_float4(0.f, 0.f, 0.f, 0.f);
    for (int c = t; c < PART; c += 128) {
        float4 v = ((const float4*)(g_dpart + (size_t)c * 384))[e4];
        s.x += v.x; s.y += v.y; s.z += v.z; s.w += v.w;
    }
    red[t] = s;
    __syncthreads();
    for (int o = 64; o; o >>= 1) {
        if (t < o) {
            float4 a = red[t], b2 = red[t + o];
            red[t] = make_float4(a.x + b2.x, a.y + b2.y, a.z + b2.z, a.w + b2.w);
        }
        __syncthreads();
    }
    if (t == 0) ((float4*)g_dsum)[e4] = red[0];
}

// B += delta(sum), W = softmax (exact masked), active-column metadata
__global__ void k_w(int applyK, int KC, int N)
{
    int t = threadIdx.x;
    if (applyK > 0)
        for (int e = t; e < applyK * 64; e += 256)
            g_B[(e >> 6) * 128 + (e & 63)] += g_dsum[e];
    __syncthreads();
    int w = t >> 5, lane = t & 31;
    if (w < KC) {
        float v0 = (lane      < N) ? g_B[w * 128 + lane]      : NEGC;
        float v1 = (lane + 32 < N) ? g_B[w * 128 + lane + 32] : NEGC;
        float m = fmaxf(fmaxf(v0, v1), NEGC);
        #pragma unroll
        for (int o = 16; o; o >>= 1) m = fmaxf(m, __shfl_xor_sync(~0u, m, o));
        float e0 = expf(v0 - m), e1 = expf(v1 - m);
        float s = e0 + e1 + 2.f * expf(NEGC - m);
        #pragma unroll
        for (int o = 16; o; o >>= 1) s += __shfl_xor_sync(~0u, s, o);
        float inv = 1.f / s;
        float w0 = e0 * inv, w1 = e1 * inv;
        g_W[w * 64 + lane]      = w0;
        g_W[w * 64 + lane + 32] = w1;
        unsigned m0 = __ballot_sync(~0u, w0 != 0.f);
        unsigned m1 = __ballot_sync(~0u, w1 != 0.f);
        if (lane == 0) {
            int c = 0;
            for (int j = 0; j < 32; j++) if ((m0 >> j) & 1) g_acol[w * 64 + c++] = j;
            for (int j = 0; j < 32; j++) if ((m1 >> j) & 1) g_acol[w * 64 + c++] = j + 32;
            g_akcnt[w] = c;
        }
    }
    __syncthreads();
    if (t == 0) {
        int tot = 0;
        for (int k = 0; k < KC; k++) tot += g_akcnt[k];
        g_sparse = (tot <= 48) ? 1 : 0;
    }
}

// one routing iteration: high = squash(W @ low), delta = sum_b high @ low^T
// dense path = R7 layout (proven); sparse path reads rows straight from L2.
template <int KC, int N, int NP2>
__global__ void __launch_bounds__(256) k_route(
        const int* __restrict__ idx, int tsel, int NB,
        int slotBase, int writeHigh, int compDelta)
{
    constexpr int LNP = (NP2 == 64) ? 6 : 5;
    constexpr int NQ = 256 / NP2;        // delta d-quarters per row (4 or 8)
    constexpr int DC = 64 / NQ;          // d per thread in delta (16 or 8)
    __shared__ __align__(16) float low[N * 65 + 3];
    __shared__ __align__(16) float wsm[KC * 64];
    __shared__ __align__(16) float scratch[4 * KC * 64];
    __shared__ __align__(16) float xfull[KC * 64];
    __shared__ __align__(16) float hsm[KC * 64];
    __shared__ __align__(16) float dscr[NQ * KC * 64];
    __shared__ int idx_s[NP2];
    __shared__ int acol_s[KC * 64];
    __shared__ int akcnt_s[8];
    __shared__ int sp_s;

    const float* table = tsel ? g_tagS : g_reviewS;
    int t = threadIdx.x;
    for (int e = t; e < KC * 64; e += 256) { wsm[e] = g_W[e]; acol_s[e] = g_acol[e]; }
    if (t < 8) akcnt_s[t] = g_akcnt[t];
    if (t == 0) sp_s = g_sparse;
    __syncthreads();
    int sp = sp_s;

    int nD = t & (NP2 - 1), qD = t >> LNP;   // qD warp-uniform, nD lane-varying
    bool vn = (nD < N);
    float dreg0 = 0.f, dreg1 = 0.f;          // delta accumulators: elems t, t+256

    for (int b = blockIdx.x; b < NB; b += gridDim.x) {
        const int* ib = idx + (size_t)b * N;

        if (sp) {
            // ---------------- sparse path: no smem tile -----------------
            if (t < N) idx_s[t] = __ldg(ib + t);
            __syncthreads();
            if (t < 64) {   // x from the few active rows, direct from L2
                float xk[KC];
                #pragma unroll
                for (int k = 0; k < KC; k++) {
                    float s = 0.f;
                    int c = akcnt_s[k];
                    for (int j = 0; j < c; j++) {
                        int n = acol_s[k * 64 + j];
                        s = fmaf(wsm[k * 64 + n],
                                 __ldg(table + (size_t)idx_s[n] * 64 + t), s);
                    }
                    xk[k] = s;
                }
                float sq = 0.f;
                #pragma unroll
                for (int k = 0; k < KC; k++) sq += xk[k] * xk[k];
                float f = sq / (1.f + sq) / sqrtf(sq + 1e-9f);
                #pragma unroll
                for (int k = 0; k < KC; k++) {
                    float h = f * xk[k];
                    hsm[k * 64 + t] = h;
                    if (writeHigh)
                        g_allu[(size_t)b * 1024 + (size_t)(slotBase + k) * 64 + t] = h;
                }
            }
            if (compDelta) {
                __syncthreads();   // hsm ready
                float ad[KC];
                #pragma unroll
                for (int k = 0; k < KC; k++) ad[k] = 0.f;
                if (vn) {
                    const float4* rowp = (const float4*)(table +
                        (size_t)idx_s[nD] * 64) + qD * (DC / 4);
                    #pragma unroll
                    for (int j4 = 0; j4 < DC; j4 += 4) {
                        float4 lv = __ldg(rowp + (j4 >> 2));
                        int d0 = qD * DC + j4;   // warp-uniform -> hsm broadcast
                        #pragma unroll
                        for (int k = 0; k < KC; k++) {
                            float4 h4 = *(const float4*)&hsm[k * 64 + d0];
                            ad[k] = fmaf(h4.x, lv.x, fmaf(h4.y, lv.y,
                                    fmaf(h4.z, lv.z, fmaf(h4.w, lv.w, ad[k]))));
                        }
                    }
                }
                #pragma unroll
                for (int k = 0; k < KC; k++)
                    dscr[qD * (KC * 64) + k * 64 + nD] = ad[k];
                __syncthreads();
                if (t < KC * 64) {
                    float s = 0.f;
                    #pragma unroll
                    for (int q = 0; q < NQ; q++) s += dscr[q * (KC * 64) + t];
                    dreg0 += s;
                }
                if (t + 256 < KC * 64) {
                    float s = 0.f;
                    #pragma unroll
                    for (int q = 0; q < NQ; q++) s += dscr[q * (KC * 64) + t + 256];
                    dreg1 += s;
                }
            }
            __syncthreads();   // idx_s/hsm reuse guard
        } else {
            // ---------------- dense path: R7 layout ---------------------
            for (int e = t; e < N * 16; e += 256) {
                int r = e >> 4, c = e & 15;
                float4 v = __ldg((const float4*)table + (size_t)__ldg(ib + r) * 16 + c);
                low[r * 65 + c * 4 + 0] = v.x; low[r * 65 + c * 4 + 1] = v.y;
                low[r * 65 + c * 4 + 2] = v.z; low[r * 65 + c * 4 + 3] = v.w;
            }
            __syncthreads();

            int d = t & 63, qx = t >> 6;
            float ax[KC];
            #pragma unroll
            for (int k = 0; k < KC; k++) ax[k] = 0.f;
            int lo = qx * 16, hi = min(N, lo + 16), nv = lo + ((hi - lo) & ~3);
            for (int n = lo; n < nv; n += 4) {
                float f0 = low[(n+0)*65+d], f1 = low[(n+1)*65+d];
                float f2 = low[(n+2)*65+d], f3 = low[(n+3)*65+d];
                #pragma unroll
                for (int k = 0; k < KC; k++) {
                    float4 w4 = *(const float4*)&wsm[k * 64 + n];
                    ax[k] = fmaf(w4.x, f0, fmaf(w4.y, f1, fmaf(w4.z, f2, fmaf(w4.w, f3, ax[k]))));
                }
            }
            for (int n = nv; n < hi; n++) {
                float f = low[n * 65 + d];
                #pragma unroll
                for (int k = 0; k < KC; k++) ax[k] = fmaf(wsm[k * 64 + n], f, ax[k]);
            }
            #pragma unroll
            for (int k = 0; k < KC; k++) scratch[qx * (KC*64) + k * 64 + d] = ax[k];
            __syncthreads();
            for (int e = t; e < KC * 64; e += 256)
                xfull[e] = scratch[e] + scratch[KC*64 + e] + scratch[2*KC*64 + e] + scratch[3*KC*64 + e];
            __syncthreads();

            if (t < 64) {
                float xk[KC];
                #pragma unroll
                for (int k = 0; k < KC; k++) xk[k] = xfull[k * 64 + t];
                float sq = 0.f;
                #pragma unroll
                for (int k = 0; k < KC; k++) sq += xk[k] * xk[k];
                float f = sq / (1.f + sq) / sqrtf(sq + 1e-9f);
                #pragma unroll
                for (int k = 0; k < KC; k++) {
                    float h = f * xk[k];
                    hsm[k * 64 + t] = h;
                    if (writeHigh)
                        g_allu[(size_t)b * 1024 + (size_t)(slotBase + k) * 64 + t] = h;
                }
            }
            if (compDelta) {
                __syncthreads();   // hsm ready
                float ad[KC];
                #pragma unroll
                for (int k = 0; k < KC; k++) ad[k] = 0.f;
                if (vn) {
                    #pragma unroll
                    for (int j4 = 0; j4 < DC; j4 += 4) {
                        int d0 = qD * DC + j4;   // warp-uniform
                        float f0 = low[nD*65+d0], f1 = low[nD*65+d0+1];
                        float f2 = low[nD*65+d0+2], f3 = low[nD*65+d0+3];
                        #pragma unroll
                        for (int k = 0; k < KC; k++) {
                            float4 h4 = *(const float4*)&hsm[k * 64 + d0];
                            ad[k] = fmaf(h4.x, f0, fmaf(h4.y, f1,
                                    fmaf(h4.z, f2, fmaf(h4.w, f3, ad[k]))));
                        }
                    }
                }
                #pragma unroll
                for (int k = 0; k < KC; k++)
                    dscr[qD * (KC * 64) + k * 64 + nD] = ad[k];
                __syncthreads();
                if (t < KC * 64) {
                    float s = 0.f;
                    #pragma unroll
                    for (int q = 0; q < NQ; q++) s += dscr[q * (KC * 64) + t];
                    dreg0 += s;
                }
                if (t + 256 < KC * 64) {
                    float s = 0.f;
                    #pragma unroll
                    for (int q = 0; q < NQ; q++) s += dscr[q * (KC * 64) + t + 256];
                    dreg1 += s;
                }
            }
            __syncthreads();   // low/hsm reuse guard
        }
    }

    if (compDelta) {
        float* dp = g_dpart + (size_t)blockIdx.x * 384;
        if (t < 384) dp[t] = (t < KC * 64) ? dreg0 : 0.f;
        int e2 = t + 256;
        if (e2 < 384) dp[e2] = (e2 < KC * 64) ? dreg1 : 0.f;
    }
}

// attention readout: 16 real capsules + 8 phantom (s=0 exactly)
__global__ void k_final(const float* __restrict__ M1, const float* __restrict__ M2,
                        float* __restrict__ out, int NB)
{
    __shared__ __align__(16) float M1s[4096];
    __shared__ float M2s[64];
    __shared__ __align__(16) float usm[16 * 68];
    __shared__ float ssm[16], attsm[16];
    int t = threadIdx.x;
    for (int e = t; e < 1024; e += 256) ((float4*)M1s)[e] = ((const float4*)M1)[e];
    if (t < 64) M2s[t] = M2[t];
    __syncthreads();
    int e4 = t & 15, k = t >> 4;
    for (int b = blockIdx.x; b < NB; b += gridDim.x) {
        float4 u4 = __ldg((const float4*)g_allu + (size_t)b * 256 + k * 16 + e4);
        *(float4*)&usm[k * 68 + e4 * 4] = u4;
        __syncthreads();
        float4 v = make_float4(0.f, 0.f, 0.f, 0.f);
        const float* urow = &usm[k * 68];
        #pragma unroll 8
        for (int dd = 0; dd < 64; dd++) {
            float u = urow[dd];
            float4 m4 = ((const float4*)M1s)[dd * 16 + e4];
            v.x = fmaf(u, m4.x, v.x); v.y = fmaf(u, m4.y, v.y);
            v.z = fmaf(u, m4.z, v.z); v.w = fmaf(u, m4.w, v.w);
        }
        float c = tanhf(v.x) * M2s[e4*4] + tanhf(v.y) * M2s[e4*4+1]
                + tanhf(v.z) * M2s[e4*4+2] + tanhf(v.w) * M2s[e4*4+3];
        #pragma unroll
        for (int o = 8; o; o >>= 1) c += __shfl_down_sync(~0u, c, o, 16);
        if (e4 == 0) ssm[k] = c * c;
        __syncthreads();
        if (t < 32) {
            float sv = (t < 16) ? ssm[t] : 0.f;
            float m = sv;
            #pragma unroll
            for (int o = 16; o; o >>= 1) m = fmaxf(m, __shfl_xor_sync(~0u, m, o));
            float ev = (t < 24) ? expf(sv - m) : 0.f;
            float s = ev;
            #pragma unroll
            for (int o = 16; o; o >>= 1) s += __shfl_xor_sync(~0u, s, o);
            if (t < 16) attsm[t] = ev / s;
        }
        __syncthreads();
        if (t < 64) {
            float o = 0.f;
            #pragma unroll
            for (int kk = 0; kk < 16; kk++) o = fmaf(attsm[kk], usm[kk * 68 + t], o);
            out[(size_t)b * 64 + t] = o;
        }
        __syncthreads();
    }
}

// review_out = mean(tag_embed[idx_rht], axis=1)
__global__ void k_review(const float* __restrict__ tag, const int* __restrict__ idx,
                         float* __restrict__ out, int NB)
{
    int t = threadIdx.x, w = t >> 5, l = t & 31;
    int b = blockIdx.x * 8 + w;
    if (b >= NB) return;
    const int* ib = idx + (size_t)b * 20;
    float a0 = 0.f, a1 = 0.f;
    #pragma unroll
    for (int r = 0; r < 20; r++) {
        const float* row = tag + (size_t)__ldg(ib + r) * 64;
        a0 += __ldg(row + l); a1 += __ldg(row + l + 32);
    }
    out[(size_t)b * 64 + l] = a0 / 20.0f;
    out[(size_t)b * 64 + l + 32] = a1 / 20.0f;
}

extern "C" void kernel_launch(void* const* d_in, const int* in_sizes, int n_in,
                              void* d_out, int out_size)
{
    const float* rev = (const float*)d_in[0];
    const float* tag = (const float*)d_in[1];
    const int* idx_urt  = (const int*)d_in[2];
    const int* idx_uqt  = (const int*)d_in[3];
    const int* idx_uprt = (const int*)d_in[4];
    const int* idx_rht  = (const int*)d_in[5];
    const float* Bm = (const float*)d_in[6];
    const float* S  = (const float*)d_in[7];
    const float* M1 = (const float*)d_in[8];
    const float* M2 = (const float*)d_in[9];
    float* out = (float*)d_out;
    int NR = in_sizes[0] / 64, NT = in_sizes[1] / 64;
    int NU = in_sizes[2] / 64, NRD = in_sizes[5] / 20;

    k_transform<<<592, 256>>>(rev, tag, S, Bm, NR, NT);
    k_review<<<(NRD + 7) / 8, 256>>>(tag, idx_rht, out + (size_t)NU * 64, NRD);

    // routing 0: idx_urt over reviewS, n=64, K=6, slots 0..5
    k_w<<<1, 256>>>(0, 6, 64);
    k_route<6, 64, 64><<<PART, 256>>>(idx_urt, 0, NU, 0, 0, 1);
    k_wred<<<96, 128>>>(); k_w<<<1, 256>>>(6, 6, 64);
    k_route<6, 64, 64><<<PART, 256>>>(idx_urt, 0, NU, 0, 0, 1);
    k_wred<<<96, 128>>>(); k_w<<<1, 256>>>(6, 6, 64);
    k_route<6, 64, 64><<<PART, 256>>>(idx_urt, 0, NU, 0, 1, 1);
    // routing 1: idx_uqt over tagS, n=32, K=5, slots 6..10
    k_wred<<<96, 128>>>(); k_w<<<1, 256>>>(6, 5, 32);
    k_route<5, 32, 32><<<PART, 256>>>(idx_uqt, 1, NU, 6, 0, 1);
    k_wred<<<96, 128>>>(); k_w<<<1, 256>>>(5, 5, 32);
    k_route<5, 32, 32><<<PART, 256>>>(idx_uqt, 1, NU, 6, 0, 1);
    k_wred<<<96, 128>>>(); k_w<<<1, 256>>>(5, 5, 32);
    k_route<5, 32, 32><<<PART, 256>>>(idx_uqt, 1, NU, 6, 1, 1);
    // routing 2: idx_uprt over reviewS, n=50, K=5, slots 11..15 (last delta dead)
    k_wred<<<96, 128>>>(); k_w<<<1, 256>>>(5, 5, 50);
    k_route<5, 50, 64><<<PART, 256>>>(idx_uprt, 0, NU, 11, 0, 1);
    k_wred<<<96, 128>>>(); k_w<<<1, 256>>>(5, 5, 50);
    k_route<5, 50, 64><<<PART, 256>>>(idx_uprt, 0, NU, 11, 0, 1);
    k_wred<<<96, 128>>>(); k_w<<<1, 256>>>(5, 5, 50);
    k_route<5, 50, 64><<<PART, 256>>>(idx_uprt, 0, NU, 11, 1, 0);

    k_final<<<592, 256>>>(M1, M2, out, NU);
}

// round 13
// speedup vs baseline: 1.5455x; 1.2429x over previous
#include <cuda_runtime.h>
#include <math.h>

#define PART 592
#define NEGC (-65535.0f)

__device__ __align__(16) float g_reviewS[30000 * 64];
__device__ __align__(16) float g_tagS[40000 * 64];
__device__ __align__(16) float g_allu[10000 * 16 * 64];
__device__ __align__(16) float g_dpart[PART * 384];
__device__ __align__(16) float g_dsum[384];
__device__ __align__(16) float g_B[8 * 128];
__device__ __align__(16) float g_W[8 * 64];
__device__ int g_akcnt[8];
__device__ int g_acol[8 * 64];
__device__ int g_sparse;

// tables @ S (hoisted transform), copy B
__global__ void k_transform(const float* __restrict__ rev, const float* __restrict__ tag,
                            const float* __restrict__ S, const float* __restrict__ Bm,
                            int NR, int NT)
{
    __shared__ __align__(16) float Ssm[4096];
    __shared__ __align__(16) float er[16 * 68];
    int t = threadIdx.x;
    if (blockIdx.x == 0)
        for (int e = t; e < 1024; e += 256) g_B[e] = Bm[e];
    for (int e = t; e < 1024; e += 256)
        ((float4*)Ssm)[e] = ((const float4*)S)[e];
    __syncthreads();
    int total = NR + NT, npass = (total + 15) >> 4;
    int quad = t & 15, slot = t >> 4;
    for (int p = blockIdx.x; p < npass; p += gridDim.x) {
        int row = p * 16 + slot;
        float4 v = make_float4(0.f, 0.f, 0.f, 0.f);
        if (row < total) {
            const float4* src = (row < NR) ? (const float4*)rev + (size_t)row * 16
                                           : (const float4*)tag + (size_t)(row - NR) * 16;
            v = __ldg(src + quad);
        }
        *(float4*)&er[slot * 68 + quad * 4] = v;
        __syncthreads();
        if (row < total) {
            float4 a = make_float4(0.f, 0.f, 0.f, 0.f);
            const float* erow = &er[slot * 68];
            #pragma unroll 8
            for (int k = 0; k < 64; k++) {
                float e = erow[k];
                float4 s4 = ((const float4*)Ssm)[k * 16 + quad];
                a.x = fmaf(e, s4.x, a.x); a.y = fmaf(e, s4.y, a.y);
                a.z = fmaf(e, s4.z, a.z); a.w = fmaf(e, s4.w, a.w);
            }
            float4* dst = (row < NR) ? (float4*)g_reviewS + (size_t)row * 16
                                     : (float4*)g_tagS + (size_t)(row - NR) * 16;
            dst[quad] = a;
        }
        __syncthreads();
    }
}

// parallel reduce of delta partials
__global__ void k_wred()
{
    __shared__ float4 red[128];
    int e4 = blockIdx.x, t = threadIdx.x;
    float4 s = make_float4(0.f, 0.f, 0.f, 0.f);
    for (int c = t; c < PART; c += 128) {
        float4 v = ((const float4*)(g_dpart + (size_t)c * 384))[e4];
        s.x += v.x; s.y += v.y; s.z += v.z; s.w += v.w;
    }
    red[t] = s;
    __syncthreads();
    for (int o = 64; o; o >>= 1) {
        if (t < o) {
            float4 a = red[t], b2 = red[t + o];
            red[t] = make_float4(a.x + b2.x, a.y + b2.y, a.z + b2.z, a.w + b2.w);
        }
        __syncthreads();
    }
    if (t == 0) ((float4*)g_dsum)[e4] = red[0];
}

// B += delta(sum), W = softmax (exact masked), active-column metadata
__global__ void k_w(int applyK, int KC, int N)
{
    int t = threadIdx.x;
    if (applyK > 0)
        for (int e = t; e < applyK * 64; e += 256)
            g_B[(e >> 6) * 128 + (e & 63)] += g_dsum[e];
    __syncthreads();
    int w = t >> 5, lane = t & 31;
    if (w < KC) {
        float v0 = (lane      < N) ? g_B[w * 128 + lane]      : NEGC;
        float v1 = (lane + 32 < N) ? g_B[w * 128 + lane + 32] : NEGC;
        float m = fmaxf(fmaxf(v0, v1), NEGC);
        #pragma unroll
        for (int o = 16; o; o >>= 1) m = fmaxf(m, __shfl_xor_sync(~0u, m, o));
        float e0 = expf(v0 - m), e1 = expf(v1 - m);
        float s = e0 + e1 + 2.f * expf(NEGC - m);
        #pragma unroll
        for (int o = 16; o; o >>= 1) s += __shfl_xor_sync(~0u, s, o);
        float inv = 1.f / s;
        float w0 = e0 * inv, w1 = e1 * inv;
        g_W[w * 64 + lane]      = w0;
        g_W[w * 64 + lane + 32] = w1;
        unsigned m0 = __ballot_sync(~0u, w0 != 0.f);
        unsigned m1 = __ballot_sync(~0u, w1 != 0.f);
        if (lane == 0) {
            int c = 0;
            for (int j = 0; j < 32; j++) if ((m0 >> j) & 1) g_acol[w * 64 + c++] = j;
            for (int j = 0; j < 32; j++) if ((m1 >> j) & 1) g_acol[w * 64 + c++] = j + 32;
            g_akcnt[w] = c;
        }
    }
    __syncthreads();
    if (t == 0) {
        int tot = 0;
        for (int k = 0; k < KC; k++) tot += g_akcnt[k];
        g_sparse = (tot <= 48) ? 1 : 0;
    }
}

// one routing iteration: high = squash(W @ low), delta = sum_b high @ low^T
// Both paths gather the batch tile coalesced into smem (65-stride, conflict-
// free both ways). Sparse skips the dense x-phase; delta is identical.
template <int KC, int N, int NP2>
__global__ void __launch_bounds__(256) k_route(
        const int* __restrict__ idx, int tsel, int NB,
        int slotBase, int writeHigh, int compDelta)
{
    constexpr int LNP = (NP2 == 64) ? 6 : 5;
    constexpr int NQ = 256 / NP2;        // delta d-quarters per row (4 or 8)
    constexpr int DC = 64 / NQ;          // d per thread in delta (16 or 8)
    __shared__ __align__(16) float low[N * 65 + 3];
    __shared__ __align__(16) float wsm[KC * 64];
    __shared__ __align__(16) float scratch[4 * KC * 64];
    __shared__ __align__(16) float xfull[KC * 64];
    __shared__ __align__(16) float hsm[KC * 64];
    __shared__ __align__(16) float dscr[NQ * KC * 64];
    __shared__ int acol_s[KC * 64];
    __shared__ int akcnt_s[8];
    __shared__ int sp_s;

    const float* table = tsel ? g_tagS : g_reviewS;
    int t = threadIdx.x;
    for (int e = t; e < KC * 64; e += 256) { wsm[e] = g_W[e]; acol_s[e] = g_acol[e]; }
    if (t < 8) akcnt_s[t] = g_akcnt[t];
    if (t == 0) sp_s = g_sparse;
    __syncthreads();
    int sp = sp_s;

    int nD = t & (NP2 - 1), qD = t >> LNP;   // qD warp-uniform, nD lane-varying
    bool vn = (nD < N);
    float dreg0 = 0.f, dreg1 = 0.f;          // delta accumulators: elems t, t+256

    for (int b = blockIdx.x; b < NB; b += gridDim.x) {
        const int* ib = idx + (size_t)b * N;
        // coalesced gather -> smem tile (warp covers 2 rows; 4 lines/instr)
        for (int e = t; e < N * 16; e += 256) {
            int r = e >> 4, c = e & 15;
            float4 v = __ldg((const float4*)table + (size_t)__ldg(ib + r) * 16 + c);
            low[r * 65 + c * 4 + 0] = v.x; low[r * 65 + c * 4 + 1] = v.y;
            low[r * 65 + c * 4 + 2] = v.z; low[r * 65 + c * 4 + 3] = v.w;
        }
        __syncthreads();

        if (!sp) {  // dense x: thread (d, qx) streams 16 n, scratch reduce
            int d = t & 63, qx = t >> 6;
            float ax[KC];
            #pragma unroll
            for (int k = 0; k < KC; k++) ax[k] = 0.f;
            int lo = qx * 16, hi = min(N, lo + 16), nv = lo + ((hi - lo) & ~3);
            for (int n = lo; n < nv; n += 4) {
                float f0 = low[(n+0)*65+d], f1 = low[(n+1)*65+d];
                float f2 = low[(n+2)*65+d], f3 = low[(n+3)*65+d];
                #pragma unroll
                for (int k = 0; k < KC; k++) {
                    float4 w4 = *(const float4*)&wsm[k * 64 + n];
                    ax[k] = fmaf(w4.x, f0, fmaf(w4.y, f1, fmaf(w4.z, f2, fmaf(w4.w, f3, ax[k]))));
                }
            }
            for (int n = nv; n < hi; n++) {
                float f = low[n * 65 + d];
                #pragma unroll
                for (int k = 0; k < KC; k++) ax[k] = fmaf(wsm[k * 64 + n], f, ax[k]);
            }
            #pragma unroll
            for (int k = 0; k < KC; k++) scratch[qx * (KC*64) + k * 64 + d] = ax[k];
            __syncthreads();
            for (int e = t; e < KC * 64; e += 256)
                xfull[e] = scratch[e] + scratch[KC*64 + e] + scratch[2*KC*64 + e] + scratch[3*KC*64 + e];
            __syncthreads();
        }

        if (t < 64) {  // (sparse x from tile) + squash + high write
            float xk[KC];
            if (sp) {
                #pragma unroll
                for (int k = 0; k < KC; k++) {
                    float s = 0.f;
                    int c = akcnt_s[k];
                    for (int j = 0; j < c; j++) {
                        int n = acol_s[k * 64 + j];
                        s = fmaf(wsm[k * 64 + n], low[n * 65 + t], s);
                    }
                    xk[k] = s;
                }
            } else {
                #pragma unroll
                for (int k = 0; k < KC; k++) xk[k] = xfull[k * 64 + t];
            }
            float sq = 0.f;
            #pragma unroll
            for (int k = 0; k < KC; k++) sq += xk[k] * xk[k];
            float f = sq / (1.f + sq) / sqrtf(sq + 1e-9f);
            #pragma unroll
            for (int k = 0; k < KC; k++) {
                float h = f * xk[k];
                if (compDelta) hsm[k * 64 + t] = h;
                if (writeHigh)
                    g_allu[(size_t)b * 1024 + (size_t)(slotBase + k) * 64 + t] = h;
            }
        }

        if (compDelta) {
            __syncthreads();   // hsm ready
            float ad[KC];
            #pragma unroll
            for (int k = 0; k < KC; k++) ad[k] = 0.f;
            if (vn) {
                #pragma unroll
                for (int j4 = 0; j4 < DC; j4 += 4) {
                    int d0 = qD * DC + j4;   // warp-uniform -> hsm broadcast
                    float f0 = low[nD*65+d0], f1 = low[nD*65+d0+1];
                    float f2 = low[nD*65+d0+2], f3 = low[nD*65+d0+3];
                    #pragma unroll
                    for (int k = 0; k < KC; k++) {
                        float4 h4 = *(const float4*)&hsm[k * 64 + d0];
                        ad[k] = fmaf(h4.x, f0, fmaf(h4.y, f1,
                                fmaf(h4.z, f2, fmaf(h4.w, f3, ad[k]))));
                    }
                }
            }
            #pragma unroll
            for (int k = 0; k < KC; k++)
                dscr[qD * (KC * 64) + k * 64 + nD] = ad[k];
            __syncthreads();
            if (t < KC * 64) {
                float s = 0.f;
                #pragma unroll
                for (int q = 0; q < NQ; q++) s += dscr[q * (KC * 64) + t];
                dreg0 += s;
            }
            if (t + 256 < KC * 64) {
                float s = 0.f;
                #pragma unroll
                for (int q = 0; q < NQ; q++) s += dscr[q * (KC * 64) + t + 256];
                dreg1 += s;
            }
        }
        __syncthreads();   // low/hsm reuse guard
    }

    if (compDelta) {
        float* dp = g_dpart + (size_t)blockIdx.x * 384;
        if (t < 384) dp[t] = (t < KC * 64) ? dreg0 : 0.f;
        int e2 = t + 256;
        if (e2 < 384) dp[e2] = (e2 < KC * 64) ? dreg1 : 0.f;
    }
}

// attention readout: 16 real capsules + 8 phantom (s=0 exactly)
__global__ void k_final(const float* __restrict__ M1, const float* __restrict__ M2,
                        float* __restrict__ out, int NB)
{
    __shared__ __align__(16) float M1s[4096];
    __shared__ float M2s[64];
    __shared__ __align__(16) float usm[16 * 68];
    __shared__ float ssm[16], attsm[16];
    int t = threadIdx.x;
    for (int e = t; e < 1024; e += 256) ((float4*)M1s)[e] = ((const float4*)M1)[e];
    if (t < 64) M2s[t] = M2[t];
    __syncthreads();
    int e4 = t & 15, k = t >> 4;
    for (int b = blockIdx.x; b < NB; b += gridDim.x) {
        float4 u4 = __ldg((const float4*)g_allu + (size_t)b * 256 + k * 16 + e4);
        *(float4*)&usm[k * 68 + e4 * 4] = u4;
        __syncthreads();
        float4 v = make_float4(0.f, 0.f, 0.f, 0.f);
        const float* urow = &usm[k * 68];
        #pragma unroll 8
        for (int dd = 0; dd < 64; dd++) {
            float u = urow[dd];
            float4 m4 = ((const float4*)M1s)[dd * 16 + e4];
            v.x = fmaf(u, m4.x, v.x); v.y = fmaf(u, m4.y, v.y);
            v.z = fmaf(u, m4.z, v.z); v.w = fmaf(u, m4.w, v.w);
        }
        float c = tanhf(v.x) * M2s[e4*4] + tanhf(v.y) * M2s[e4*4+1]
                + tanhf(v.z) * M2s[e4*4+2] + tanhf(v.w) * M2s[e4*4+3];
        #pragma unroll
        for (int o = 8; o; o >>= 1) c += __shfl_down_sync(~0u, c, o, 16);
        if (e4 == 0) ssm[k] = c * c;
        __syncthreads();
        if (t < 32) {
            float sv = (t < 16) ? ssm[t] : 0.f;
            float m = sv;
            #pragma unroll
            for (int o = 16; o; o >>= 1) m = fmaxf(m, __shfl_xor_sync(~0u, m, o));
            float ev = (t < 24) ? expf(sv - m) : 0.f;
            float s = ev;
            #pragma unroll
            for (int o = 16; o; o >>= 1) s += __shfl_xor_sync(~0u, s, o);
            if (t < 16) attsm[t] = ev / s;
        }
        __syncthreads();
        if (t < 64) {
            float o = 0.f;
            #pragma unroll
            for (int kk = 0; kk < 16; kk++) o = fmaf(attsm[kk], usm[kk * 68 + t], o);
            out[(size_t)b * 64 + t] = o;
        }
        __syncthreads();
    }
}

// review_out = mean(tag_embed[idx_rht], axis=1)
__global__ void k_review(const float* __restrict__ tag, const int* __restrict__ idx,
                         float* __restrict__ out, int NB)
{
    int t = threadIdx.x, w = t >> 5, l = t & 31;
    int b = blockIdx.x * 8 + w;
    if (b >= NB) return;
    const int* ib = idx + (size_t)b * 20;
    float a0 = 0.f, a1 = 0.f;
    #pragma unroll
    for (int r = 0; r < 20; r++) {
        const float* row = tag + (size_t)__ldg(ib + r) * 64;
        a0 += __ldg(row + l); a1 += __ldg(row + l + 32);
    }
    out[(size_t)b * 64 + l] = a0 / 20.0f;
    out[(size_t)b * 64 + l + 32] = a1 / 20.0f;
}

extern "C" void kernel_launch(void* const* d_in, const int* in_sizes, int n_in,
                              void* d_out, int out_size)
{
    const float* rev = (const float*)d_in[0];
    const float* tag = (const float*)d_in[1];
    const int* idx_urt  = (const int*)d_in[2];
    const int* idx_uqt  = (const int*)d_in[3];
    const int* idx_uprt = (const int*)d_in[4];
    const int* idx_rht  = (const int*)d_in[5];
    const float* Bm = (const float*)d_in[6];
    const float* S  = (const float*)d_in[7];
    const float* M1 = (const float*)d_in[8];
    const float* M2 = (const float*)d_in[9];
    float* out = (float*)d_out;
    int NR = in_sizes[0] / 64, NT = in_sizes[1] / 64;
    int NU = in_sizes[2] / 64, NRD = in_sizes[5] / 20;

    k_transform<<<592, 256>>>(rev, tag, S, Bm, NR, NT);
    k_review<<<(NRD + 7) / 8, 256>>>(tag, idx_rht, out + (size_t)NU * 64, NRD);

    // routing 0: idx_urt over reviewS, n=64, K=6, slots 0..5
    k_w<<<1, 256>>>(0, 6, 64);
    k_route<6, 64, 64><<<PART, 256>>>(idx_urt, 0, NU, 0, 0, 1);
    k_wred<<<96, 128>>>(); k_w<<<1, 256>>>(6, 6, 64);
    k_route<6, 64, 64><<<PART, 256>>>(idx_urt, 0, NU, 0, 0, 1);
    k_wred<<<96, 128>>>(); k_w<<<1, 256>>>(6, 6, 64);
    k_route<6, 64, 64><<<PART, 256>>>(idx_urt, 0, NU, 0, 1, 1);
    // routing 1: idx_uqt over tagS, n=32, K=5, slots 6..10
    k_wred<<<96, 128>>>(); k_w<<<1, 256>>>(6, 5, 32);
    k_route<5, 32, 32><<<PART, 256>>>(idx_uqt, 1, NU, 6, 0, 1);
    k_wred<<<96, 128>>>(); k_w<<<1, 256>>>(5, 5, 32);
    k_route<5, 32, 32><<<PART, 256>>>(idx_uqt, 1, NU, 6, 0, 1);
    k_wred<<<96, 128>>>(); k_w<<<1, 256>>>(5, 5, 32);
    k_route<5, 32, 32><<<PART, 256>>>(idx_uqt, 1, NU, 6, 1, 1);
    // routing 2: idx_uprt over reviewS, n=50, K=5, slots 11..15 (last delta dead)
    k_wred<<<96, 128>>>(); k_w<<<1, 256>>>(5, 5, 50);
    k_route<5, 50, 64><<<PART, 256>>>(idx_uprt, 0, NU, 11, 0, 1);
    k_wred<<<96, 128>>>(); k_w<<<1, 256>>>(5, 5, 50);
    k_route<5, 50, 64><<<PART, 256>>>(idx_uprt, 0, NU, 11, 0, 1);
    k_wred<<<96, 128>>>(); k_w<<<1, 256>>>(5, 5, 50);
    k_route<5, 50, 64><<<PART, 256>>>(idx_uprt, 0, NU, 11, 1, 0);

    k_final<<<592, 256>>>(M1, M2, out, NU);
}